// round 11
// baseline (speedup 1.0000x reference)
#include <cuda_runtime.h>

// GRUAdder: B = 1048576, T=4, I=2, H=16.
// L=8 lanes per row (lane q owns h[2q],h[2q+1], gates {2q,2q+1} of r/z/n),
// D=4 rows per thread. k-parity f32x2 accumulators: the shfl64 of the owner
// lane's packed h feeds ffma2 directly (no repacking). Weights streamed from
// shared, each 48B weight slice amortized over 4 rows (2 B per ffma2).
// Sigmoids via tanh.approx (0.5 scale pre-folded into staged weights);
// n-gate tanh via ex2/rcp with -2*log2(e) pre-folded.

#define TT 4
#define II 2
#define HH 16
#define LROWS 4   // iterations; rows per warp = 16 * LROWS = 64

#define SRZ 0.5f
#define SN  (-2.8853900817779268f)   // -2*log2(e)

typedef unsigned long long ull;

__device__ __forceinline__ ull ffma2(ull a, ull b, ull c) {
    ull d;
    asm("fma.rn.f32x2 %0, %1, %2, %3;" : "=l"(d) : "l"(a), "l"(b), "l"(c));
    return d;
}
__device__ __forceinline__ ull pk2(float lo, float hi) {
    ull r;
    asm("mov.b64 %0, {%1, %2};" : "=l"(r) : "f"(lo), "f"(hi));
    return r;
}
__device__ __forceinline__ void upk2(float& lo, float& hi, ull v) {
    asm("mov.b64 {%0, %1}, %2;" : "=f"(lo), "=f"(hi) : "l"(v));
}
__device__ __forceinline__ float hadd2(ull v) {
    float lo, hi;
    upk2(lo, hi, v);
    return lo + hi;
}
__device__ __forceinline__ float tanhapx(float x) {
    float r;
    asm("tanh.approx.f32 %0, %1;" : "=f"(r) : "f"(x));
    return r;
}
// argument already scaled by -2*log2(e): returns tanh(y) where a = SN*y
__device__ __forceinline__ float ftanh_prescaled(float a) {
    float e, r;
    asm("ex2.approx.f32 %0, %1;" : "=f"(e) : "f"(a));
    asm("rcp.approx.f32 %0, %1;" : "=f"(r) : "f"(1.0f + e));
    return fmaf(2.0f, r, -1.0f);
}

__global__ void __launch_bounds__(128) gru_adder_kernel(
    const float* __restrict__ x,        // [B, 4, 2]
    const float* __restrict__ w_ih,     // [48, 2]
    const float* __restrict__ w_hh,     // [48, 16]
    const float* __restrict__ b_ih,     // [48]
    const float* __restrict__ b_hh,     // [48]
    const float* __restrict__ w_sum,    // [1, 16]
    const float* __restrict__ b_sum,    // [1]
    const float* __restrict__ w_carry,  // [1, 16]
    const float* __restrict__ b_carry,  // [1]
    float* __restrict__ hid,            // [B, 4, 16]
    float* __restrict__ sumo,           // [B, 4]
    float* __restrict__ carryo,         // [B]
    float* __restrict__ olog,           // [B, 5]
    long long B)
{
    // sh_wp[kp*48 + q*6 + s]: s = {R0,R1,Z0,Z1,N0,N1}; gate j = (s>>1)*16+2q+(s&1)
    // value = (scale*w_hh[j][2kp], scale*w_hh[j][2kp+1]); scale = 0.5 (r,z), SN (n)
    __shared__ __align__(16) ull sh_wp[8 * 8 * 6];
    __shared__ __align__(16) ull sh_uih[8 * 6];
    __shared__ __align__(16) ull sh_bias[8 * 6];
    __shared__ __align__(16) ull sh_biN[16];
    __shared__ __align__(16) ull sh_ws[8], sh_wc[8];
    __shared__ float sh_bs, sh_bc;

    const int tidb = threadIdx.x;
    for (int idx = tidb; idx < 384; idx += 128) {
        int kp = idx / 48, rem = idx % 48, qq = rem / 6, s = rem % 6;
        int cat = s >> 1;
        int j = cat * 16 + 2 * qq + (s & 1);
        float sc = (cat < 2) ? SRZ : SN;
        sh_wp[idx] = pk2(sc * w_hh[j * HH + 2 * kp], sc * w_hh[j * HH + 2 * kp + 1]);
    }
    if (tidb < 48) {
        int qq = tidb / 6, s = tidb % 6;
        int cat = s >> 1;
        int j = cat * 16 + 2 * qq + (s & 1);
        float sc = (cat < 2) ? SRZ : SN;
        sh_uih[tidb] = pk2(sc * w_ih[j * II + 0], sc * w_ih[j * II + 1]);
        if (cat < 2) {
            sh_bias[tidb] = pk2(SRZ * (b_ih[j] + b_hh[j]), 0.0f);
        } else {
            sh_bias[tidb] = pk2(SN * b_hh[j], 0.0f);
            sh_biN[qq * 2 + (s & 1)] = pk2(SN * b_ih[j], 0.0f);
        }
    }
    if (tidb < 8) {
        sh_ws[tidb] = pk2(w_sum[2 * tidb],   w_sum[2 * tidb + 1]);
        sh_wc[tidb] = pk2(w_carry[2 * tidb], w_carry[2 * tidb + 1]);
        if (tidb == 0) { sh_bs = b_sum[0]; sh_bc = b_carry[0]; }
    }
    __syncthreads();

    const int lane    = tidb & 31;
    const int q       = lane & 7;
    const int grpbase = lane & 24;
    const int grp     = lane >> 3;

    const ull uR0 = sh_uih[q * 6 + 0], uR1 = sh_uih[q * 6 + 1];
    const ull uZ0 = sh_uih[q * 6 + 2], uZ1 = sh_uih[q * 6 + 3];
    const ull uN0 = sh_uih[q * 6 + 4], uN1 = sh_uih[q * 6 + 5];
    const ull bR0 = sh_bias[q * 6 + 0], bR1 = sh_bias[q * 6 + 1];
    const ull bZ0 = sh_bias[q * 6 + 2], bZ1 = sh_bias[q * 6 + 3];
    const ull bN0 = sh_bias[q * 6 + 4], bN1 = sh_bias[q * 6 + 5];
    const ull biN0 = sh_biN[q * 2 + 0], biN1 = sh_biN[q * 2 + 1];
    float wsl, wsh, wcl, wch;
    upk2(wsl, wsh, sh_ws[q]);
    upk2(wcl, wch, sh_wc[q]);
    const float bs = sh_bs, bc = sh_bc;

    const ull* wbase = &sh_wp[q * 6];

    const int  warp_global = blockIdx.x * (blockDim.x >> 5) + (tidb >> 5);
    const long long rowbase0 = (long long)warp_global * (16 * LROWS);
    if (rowbase0 >= B) return;

    #pragma unroll 1
    for (int it = 0; it < LROWS; it++) {
        const long long r0 = rowbase0 + it * 16 + grp;   // rows r0 + 4*i, i=0..3
        if (r0 >= B) break;

        ull h[4] = {0, 0, 0, 0};   // (h[2q], h[2q+1]) packed, per row

        #pragma unroll
        for (int t = 0; t < TT; t++) {
            ull acc[4][6];   // R0,R1,Z0,Z1,N0,N1 (k-parity packed)
            ull gn[4][2];    // n-gate input part (prescaled)

            #pragma unroll
            for (int i = 0; i < 4; i++) {
                const long long row = r0 + 4 * i;
                const long long rs  = (row < B) ? row : r0;
                const float2 xv = *reinterpret_cast<const float2*>(x + rs * (TT*II) + t*II);
                const ull xp = pk2(xv.x, xv.y);
                acc[i][0] = ffma2(uR0, xp, bR0);
                acc[i][1] = ffma2(uR1, xp, bR1);
                acc[i][2] = ffma2(uZ0, xp, bZ0);
                acc[i][3] = ffma2(uZ1, xp, bZ1);
                acc[i][4] = bN0;
                acc[i][5] = bN1;
                gn[i][0] = ffma2(uN0, xp, biN0);
                gn[i][1] = ffma2(uN1, xp, biN1);
            }

            // matvec over 8 k-pairs; each 48B weight slice feeds 4 rows
            #pragma unroll
            for (int kp = 0; kp < 8; kp++) {
                const ull* wp = wbase + kp * 48;
                const ull w0 = wp[0], w1 = wp[1], w2 = wp[2];
                const ull w3 = wp[3], w4 = wp[4], w5 = wp[5];
                #pragma unroll
                for (int i = 0; i < 4; i++) {
                    const ull hb = __shfl_sync(0xffffffffu, h[i], grpbase | kp);
                    acc[i][0] = ffma2(w0, hb, acc[i][0]);
                    acc[i][1] = ffma2(w1, hb, acc[i][1]);
                    acc[i][2] = ffma2(w2, hb, acc[i][2]);
                    acc[i][3] = ffma2(w3, hb, acc[i][3]);
                    acc[i][4] = ffma2(w4, hb, acc[i][4]);
                    acc[i][5] = ffma2(w5, hb, acc[i][5]);
                }
            }

            // epilogue + heads, per row
            #pragma unroll
            for (int i = 0; i < 4; i++) {
                const long long row = r0 + 4 * i;
                float hp0, hp1;
                upk2(hp0, hp1, h[i]);
                float rg0 = fmaf(tanhapx(hadd2(acc[i][0])), 0.5f, 0.5f);
                float rg1 = fmaf(tanhapx(hadd2(acc[i][1])), 0.5f, 0.5f);
                float zg0 = fmaf(tanhapx(hadd2(acc[i][2])), 0.5f, 0.5f);
                float zg1 = fmaf(tanhapx(hadd2(acc[i][3])), 0.5f, 0.5f);
                float n0  = ftanh_prescaled(fmaf(rg0, hadd2(acc[i][4]), hadd2(gn[i][0])));
                float n1  = ftanh_prescaled(fmaf(rg1, hadd2(acc[i][5]), hadd2(gn[i][1])));
                float h0  = fmaf(zg0, hp0 - n0, n0);   // (1-z)*n + z*h
                float h1  = fmaf(zg1, hp1 - n1, n1);
                h[i] = pk2(h0, h1);

                float sp = fmaf(h0, wsl, h1 * wsh);
                sp += __shfl_xor_sync(0xffffffffu, sp, 1);
                sp += __shfl_xor_sync(0xffffffffu, sp, 2);
                sp += __shfl_xor_sync(0xffffffffu, sp, 4);

                if (row < B) {
                    if (hid)
                        *reinterpret_cast<float2*>(hid + row * (TT*HH) + t*HH + 2*q) =
                            make_float2(h0, h1);
                    if (q == 0) {
                        if (sumo) sumo[row * TT + t] = bs + sp;
                    } else if (q == 1) {
                        if (olog) olog[row * (TT+1) + t] = bs + sp;
                    }
                }
            }
        }

        // carry head
        #pragma unroll
        for (int i = 0; i < 4; i++) {
            const long long row = r0 + 4 * i;
            float h0, h1;
            upk2(h0, h1, h[i]);
            float cp = fmaf(h0, wcl, h1 * wch);
            cp += __shfl_xor_sync(0xffffffffu, cp, 1);
            cp += __shfl_xor_sync(0xffffffffu, cp, 2);
            cp += __shfl_xor_sync(0xffffffffu, cp, 4);
            if (row < B) {
                if (q == 2) {
                    if (carryo) carryo[row] = bc + cp;
                } else if (q == 3) {
                    if (olog) olog[row * (TT+1) + TT] = bc + cp;
                }
            }
        }
    }
}

extern "C" void kernel_launch(void* const* d_in, const int* in_sizes, int n_in,
                              void* d_out, int out_size) {
    const float* x       = (const float*)d_in[0];
    const float* w_ih    = (const float*)d_in[1];
    const float* w_hh    = (const float*)d_in[2];
    const float* b_ih    = (const float*)d_in[3];
    const float* b_hh    = (const float*)d_in[4];
    const float* w_sum   = (const float*)d_in[5];
    const float* b_sum   = (const float*)d_in[6];
    const float* w_carry = (const float*)d_in[7];
    const float* b_carry = (const float*)d_in[8];

    long long B = (long long)in_sizes[0] / (TT * II);
    float* out = (float*)d_out;
    long long os = (long long)out_size;

    // Output layout: concatenation of flattened (hidden_table, sum_logits,
    // carry_logit, output_logits) = 74 floats per row; fall back otherwise.
    float *hid = nullptr, *sum = nullptr, *car = nullptr, *olog = nullptr;
    if (os >= B * 74) {
        hid = out; sum = out + B * 64; car = out + B * 68; olog = out + B * 69;
    } else if (os >= B * 64) {
        hid = out;
    } else if (os >= B * 5) {
        olog = out;
    } else if (os >= B * 4) {
        sum = out;
    } else {
        car = out;
    }

    const int threads = 128;                        // 4 warps per CTA
    const long long rows_per_warp = 16 * LROWS;     // 64
    long long warps = (B + rows_per_warp - 1) / rows_per_warp;
    long long ctas  = (warps + 3) / 4;
    gru_adder_kernel<<<(int)ctas, threads>>>(x, w_ih, w_hh, b_ih, b_hh,
                                             w_sum, b_sum, w_carry, b_carry,
                                             hid, sum, car, olog, B);
}

// round 12
// speedup vs baseline: 1.5615x; 1.5615x over previous
#include <cuda_runtime.h>

// GRUAdder: B = 1048576, T=4, I=2, H=16.
// L=4 lanes per row: lane q owns h[4q..4q+3] and gates {4q..4q+3} of r/z/n.
// D=2 rows per thread. k-parity f32x2 accumulators (shfl64 of owner's packed
// h feeds ffma2 directly). ALL weights/biases streamed from shared each use
// (nothing weight-like held in registers) to keep regs ~<=128 and occupancy
// at 4+ warps/SMSP. Sigmoid via tanh.approx with 0.5 pre-folded into staged
// weights; n-gate tanh via ex2/rcp with -2*log2(e) pre-folded.

#define TT 4
#define II 2
#define HH 16
#define LROWS 4   // iterations; rows per warp = 16 * LROWS = 64

#define SRZ 0.5f
#define SN  (-2.8853900817779268f)   // -2*log2(e)

typedef unsigned long long ull;

__device__ __forceinline__ ull ffma2(ull a, ull b, ull c) {
    ull d;
    asm("fma.rn.f32x2 %0, %1, %2, %3;" : "=l"(d) : "l"(a), "l"(b), "l"(c));
    return d;
}
__device__ __forceinline__ ull pk2(float lo, float hi) {
    ull r;
    asm("mov.b64 %0, {%1, %2};" : "=l"(r) : "f"(lo), "f"(hi));
    return r;
}
__device__ __forceinline__ void upk2(float& lo, float& hi, ull v) {
    asm("mov.b64 {%0, %1}, %2;" : "=f"(lo), "=f"(hi) : "l"(v));
}
__device__ __forceinline__ float hadd2(ull v) {
    float lo, hi;
    upk2(lo, hi, v);
    return lo + hi;
}
__device__ __forceinline__ float tanhapx(float x) {
    float r;
    asm("tanh.approx.f32 %0, %1;" : "=f"(r) : "f"(x));
    return r;
}
// argument already scaled by -2*log2(e): returns tanh(y) where a = SN*y
__device__ __forceinline__ float ftanh_prescaled(float a) {
    float e, r;
    asm("ex2.approx.f32 %0, %1;" : "=f"(e) : "f"(a));
    asm("rcp.approx.f32 %0, %1;" : "=f"(r) : "f"(1.0f + e));
    return fmaf(2.0f, r, -1.0f);
}

__global__ void __launch_bounds__(128) gru_adder_kernel(
    const float* __restrict__ x,        // [B, 4, 2]
    const float* __restrict__ w_ih,     // [48, 2]
    const float* __restrict__ w_hh,     // [48, 16]
    const float* __restrict__ b_ih,     // [48]
    const float* __restrict__ b_hh,     // [48]
    const float* __restrict__ w_sum,    // [1, 16]
    const float* __restrict__ b_sum,    // [1]
    const float* __restrict__ w_carry,  // [1, 16]
    const float* __restrict__ b_carry,  // [1]
    float* __restrict__ hid,            // [B, 4, 16]
    float* __restrict__ sumo,           // [B, 4]
    float* __restrict__ carryo,         // [B]
    float* __restrict__ olog,           // [B, 5]
    long long B)
{
    // Slot s = cat*4 + m (cat: 0=r,1=z,2=n; m=0..3). Gate j = cat*16 + 4q + m.
    // sh_wp[kp*48 + q*12 + s] = (sc*w_hh[j][2kp], sc*w_hh[j][2kp+1])
    //   sc = 0.5 for r/z, SN for n.
    __shared__ __align__(16) ull sh_wp[8 * 4 * 12];
    __shared__ __align__(16) ull sh_wx[4 * 12];   // (sc*w_ih[j][0], sc*w_ih[j][1])
    __shared__ __align__(16) ull sh_b2[4 * 12];   // r,z: (0.5*(bi+bh),0); n: (SN*bh,0)
    __shared__ __align__(16) ull sh_gb[16];       // (SN*b_ih[32+idx], 0)
    __shared__ __align__(16) float sh_wsum[16], sh_wcar[16];
    __shared__ float sh_bs, sh_bc;

    const int tidb = threadIdx.x;
    for (int idx = tidb; idx < 384; idx += 128) {
        int kp = idx / 48, rem = idx % 48, qq = rem / 12, s = rem % 12;
        int cat = s >> 2, m = s & 3;
        int j = cat * 16 + 4 * qq + m;
        float sc = (cat < 2) ? SRZ : SN;
        sh_wp[idx] = pk2(sc * w_hh[j * HH + 2 * kp], sc * w_hh[j * HH + 2 * kp + 1]);
    }
    if (tidb < 48) {
        int qq = tidb / 12, s = tidb % 12;
        int cat = s >> 2, m = s & 3;
        int j = cat * 16 + 4 * qq + m;
        float sc = (cat < 2) ? SRZ : SN;
        sh_wx[tidb] = pk2(sc * w_ih[j * II + 0], sc * w_ih[j * II + 1]);
        sh_b2[tidb] = (cat < 2) ? pk2(SRZ * (b_ih[j] + b_hh[j]), 0.0f)
                                : pk2(SN * b_hh[j], 0.0f);
    }
    if (tidb < 16) {
        sh_gb[tidb]   = pk2(SN * b_ih[32 + tidb], 0.0f);
        sh_wsum[tidb] = w_sum[tidb];
        sh_wcar[tidb] = w_carry[tidb];
        if (tidb == 0) { sh_bs = b_sum[0]; sh_bc = b_carry[0]; }
    }
    __syncthreads();

    const int lane    = tidb & 31;
    const int q       = lane & 3;       // gate-slice owner within 4-lane group
    const int grpbase = lane & 28;
    const int g       = (lane >> 2);    // group 0..7 within warp

    const ull* wkp = sh_wp + q * 12;    // + kp*48 inside loop
    const ull* wxp = sh_wx + q * 12;
    const ull* b2p = sh_b2 + q * 12;
    const ull* gbp = sh_gb + q * 4;
    const float ws0 = sh_wsum[4*q+0], ws1 = sh_wsum[4*q+1];
    const float ws2 = sh_wsum[4*q+2], ws3 = sh_wsum[4*q+3];
    const float wc0 = sh_wcar[4*q+0], wc1 = sh_wcar[4*q+1];
    const float wc2 = sh_wcar[4*q+2], wc3 = sh_wcar[4*q+3];
    const float bs = sh_bs, bc = sh_bc;

    const int  warp_global = blockIdx.x * (blockDim.x >> 5) + (tidb >> 5);
    const long long rowbase0 = (long long)warp_global * (16 * LROWS);
    if (rowbase0 >= B) return;

    #pragma unroll 1
    for (int it = 0; it < LROWS; it++) {
        const long long rowA = rowbase0 + it * 16 + g;
        const long long rowB = rowA + 8;
        // Clamped addresses (B=1M is divisible by 64, so normally all valid;
        // clamps keep OOB safe without divergence that would break shfl).
        const long long rAs = (rowA < B) ? rowA : 0;
        const long long rBs = (rowB < B) ? rowB : 0;
        const bool okA = (rowA < B), okB = (rowB < B);

        ull hL[2] = {0, 0};   // (h[4q],   h[4q+1]) per row
        ull hH[2] = {0, 0};   // (h[4q+2], h[4q+3]) per row

        #pragma unroll 1
        for (int t = 0; t < TT; t++) {
            const float2 xA = *reinterpret_cast<const float2*>(x + rAs * (TT*II) + t*II);
            const float2 xB = *reinterpret_cast<const float2*>(x + rBs * (TT*II) + t*II);
            const ull xpA = pk2(xA.x, xA.y);
            const ull xpB = pk2(xB.x, xB.y);

            ull acc[2][12];   // k-parity packed: s = cat*4+m
            ull gin[2][4];    // n-gate input part (prescaled by SN)

            #pragma unroll
            for (int s = 0; s < 8; s++) {      // r,z gates: x + bias
                const ull w = wxp[s], b = b2p[s];
                acc[0][s] = ffma2(w, xpA, b);
                acc[1][s] = ffma2(w, xpB, b);
            }
            #pragma unroll
            for (int m = 0; m < 4; m++) {      // n gates: split rec/input
                const ull b = b2p[8 + m];
                acc[0][8 + m] = b;
                acc[1][8 + m] = b;
                const ull w = wxp[8 + m], gb = gbp[m];
                gin[0][m] = ffma2(w, xpA, gb);
                gin[1][m] = ffma2(w, xpB, gb);
            }

            // matvec over 8 k-pairs; 96B weight slice feeds both rows
            #pragma unroll
            for (int kp = 0; kp < 8; kp++) {
                const int src = grpbase | (kp >> 1);
                const ull hbA = __shfl_sync(0xffffffffu, (kp & 1) ? hH[0] : hL[0], src);
                const ull hbB = __shfl_sync(0xffffffffu, (kp & 1) ? hH[1] : hL[1], src);
                const ull* wp = wkp + kp * 48;
                #pragma unroll
                for (int s = 0; s < 12; s++) {
                    const ull w = wp[s];
                    acc[0][s] = ffma2(w, hbA, acc[0][s]);
                    acc[1][s] = ffma2(w, hbB, acc[1][s]);
                }
            }

            // epilogue + heads per row
            #pragma unroll
            for (int i = 0; i < 2; i++) {
                float hp0, hp1, hp2, hp3;
                upk2(hp0, hp1, hL[i]);
                upk2(hp2, hp3, hH[i]);
                const float r0 = fmaf(tanhapx(hadd2(acc[i][0])), 0.5f, 0.5f);
                const float r1 = fmaf(tanhapx(hadd2(acc[i][1])), 0.5f, 0.5f);
                const float r2 = fmaf(tanhapx(hadd2(acc[i][2])), 0.5f, 0.5f);
                const float r3 = fmaf(tanhapx(hadd2(acc[i][3])), 0.5f, 0.5f);
                const float z0 = fmaf(tanhapx(hadd2(acc[i][4])), 0.5f, 0.5f);
                const float z1 = fmaf(tanhapx(hadd2(acc[i][5])), 0.5f, 0.5f);
                const float z2 = fmaf(tanhapx(hadd2(acc[i][6])), 0.5f, 0.5f);
                const float z3 = fmaf(tanhapx(hadd2(acc[i][7])), 0.5f, 0.5f);
                const float n0 = ftanh_prescaled(fmaf(r0, hadd2(acc[i][8]),  hadd2(gin[i][0])));
                const float n1 = ftanh_prescaled(fmaf(r1, hadd2(acc[i][9]),  hadd2(gin[i][1])));
                const float n2 = ftanh_prescaled(fmaf(r2, hadd2(acc[i][10]), hadd2(gin[i][2])));
                const float n3 = ftanh_prescaled(fmaf(r3, hadd2(acc[i][11]), hadd2(gin[i][3])));
                const float h0 = fmaf(z0, hp0 - n0, n0);   // (1-z)*n + z*h
                const float h1 = fmaf(z1, hp1 - n1, n1);
                const float h2 = fmaf(z2, hp2 - n2, n2);
                const float h3 = fmaf(z3, hp3 - n3, n3);
                hL[i] = pk2(h0, h1);
                hH[i] = pk2(h2, h3);

                float sp = fmaf(h3, ws3, fmaf(h2, ws2, fmaf(h1, ws1, h0 * ws0)));
                sp += __shfl_xor_sync(0xffffffffu, sp, 1);
                sp += __shfl_xor_sync(0xffffffffu, sp, 2);

                const long long row = i ? rowB : rowA;
                const bool ok = i ? okB : okA;
                if (ok) {
                    if (hid)
                        *reinterpret_cast<float4*>(hid + row * (TT*HH) + t*HH + 4*q) =
                            make_float4(h0, h1, h2, h3);
                    if (q == 0) {
                        if (sumo) sumo[row * TT + t] = bs + sp;
                    } else if (q == 1) {
                        if (olog) olog[row * (TT+1) + t] = bs + sp;
                    }
                }
            }
        }

        // carry head
        #pragma unroll
        for (int i = 0; i < 2; i++) {
            float h0, h1, h2, h3;
            upk2(h0, h1, hL[i]);
            upk2(h2, h3, hH[i]);
            float cp = fmaf(h3, wc3, fmaf(h2, wc2, fmaf(h1, wc1, h0 * wc0)));
            cp += __shfl_xor_sync(0xffffffffu, cp, 1);
            cp += __shfl_xor_sync(0xffffffffu, cp, 2);
            const long long row = i ? rowB : rowA;
            const bool ok = i ? okB : okA;
            if (ok) {
                if (q == 2) {
                    if (carryo) carryo[row] = bc + cp;
                } else if (q == 3) {
                    if (olog) olog[row * (TT+1) + TT] = bc + cp;
                }
            }
        }
    }
}

extern "C" void kernel_launch(void* const* d_in, const int* in_sizes, int n_in,
                              void* d_out, int out_size) {
    const float* x       = (const float*)d_in[0];
    const float* w_ih    = (const float*)d_in[1];
    const float* w_hh    = (const float*)d_in[2];
    const float* b_ih    = (const float*)d_in[3];
    const float* b_hh    = (const float*)d_in[4];
    const float* w_sum   = (const float*)d_in[5];
    const float* b_sum   = (const float*)d_in[6];
    const float* w_carry = (const float*)d_in[7];
    const float* b_carry = (const float*)d_in[8];

    long long B = (long long)in_sizes[0] / (TT * II);
    float* out = (float*)d_out;
    long long os = (long long)out_size;

    // Output layout: concatenation of flattened (hidden_table, sum_logits,
    // carry_logit, output_logits) = 74 floats per row; fall back otherwise.
    float *hid = nullptr, *sum = nullptr, *car = nullptr, *olog = nullptr;
    if (os >= B * 74) {
        hid = out; sum = out + B * 64; car = out + B * 68; olog = out + B * 69;
    } else if (os >= B * 64) {
        hid = out;
    } else if (os >= B * 5) {
        olog = out;
    } else if (os >= B * 4) {
        sum = out;
    } else {
        car = out;
    }

    const int threads = 128;                        // 4 warps per CTA
    const long long rows_per_warp = 16 * LROWS;     // 64
    long long warps = (B + rows_per_warp - 1) / rows_per_warp;
    long long ctas  = (warps + 3) / 4;
    gru_adder_kernel<<<(int)ctas, threads>>>(x, w_ih, w_hh, b_ih, b_hh,
                                             w_sum, b_sum, w_carry, b_carry,
                                             hid, sum, car, olog, B);
}